// round 3
// baseline (speedup 1.0000x reference)
#include <cuda_runtime.h>
#include <cuda_bf16.h>
#include <cstdint>

// Problem constants (fixed by the dataset)
#define NMAX 50000
#define DDIM 64

// Scratch (no cudaMalloc allowed)
__device__ float4 g_x4[NMAX * (DDIM / 4)];
__device__ float4 g_agg4[NMAX * (DDIM / 4)];
__device__ float  g_deg[NMAX];
__device__ int    g_is64;   // 1 if edge_index is int64, 0 if int32

// ---------------------------------------------------------------------------
// Kernel A: detect edge_index dtype. View buffer as int32: for int64 data,
// every odd int32 position is a zero high-word (indices < 50000). For int32
// pairs, odd positions are random dst ids — all-zero over 64 edges ~ never.
// ---------------------------------------------------------------------------
__global__ void detect_kernel(const int* __restrict__ ei32, int nE) {
    int all_zero = 1;
    int lim = (nE < 64) ? nE : 64;
    for (int i = 0; i < lim; i++)
        if (ei32[2 * i + 1] != 0) { all_zero = 0; break; }
    g_is64 = all_zero;
}

// ---------------------------------------------------------------------------
// Kernel 0: zero agg + degree (graph replays must not accumulate)
// ---------------------------------------------------------------------------
__global__ void zero_kernel(float4* agg4, float* deg, int n) {
    int tid = blockIdx.x * blockDim.x + threadIdx.x;
    int n4 = n * (DDIM / 4);
    for (int i = tid; i < n4; i += gridDim.x * blockDim.x)
        agg4[i] = make_float4(0.f, 0.f, 0.f, 0.f);
    for (int i = tid; i < n; i += gridDim.x * blockDim.x)
        deg[i] = 0.f;
}

// ---------------------------------------------------------------------------
// Kernel 1: x = nf @ W^T + b_lin   (M=50000, N=64, K=64)
// 256 threads/block, 16 rows per block, thread = 1 row x 4 cols.
// W transposed into smem with pad-68 stride (conflict-free float4 reads).
// ---------------------------------------------------------------------------
__global__ __launch_bounds__(256) void gemm_kernel(
    const float* __restrict__ nf, const float* __restrict__ W,
    const float* __restrict__ b, float4* __restrict__ x4, int n)
{
    __shared__ float Wt[64 * 68];       // Wt[k*68 + col] = W[col*64 + k]
    __shared__ float nfs[16 * 64];

    int t = threadIdx.x;
    for (int i = t; i < 64 * 64; i += 256) {
        int col = i >> 6, k = i & 63;
        Wt[k * 68 + col] = W[i];        // coalesced gmem read
    }
    int row0 = blockIdx.x * 16;
    for (int i = t; i < 16 * 64; i += 256) {
        int r = row0 + (i >> 6);
        nfs[i] = (r < n) ? nf[r * 64 + (i & 63)] : 0.f;
    }
    __syncthreads();

    int rl = t >> 4;                    // 0..15 local row
    int c4 = (t & 15) * 4;              // col base
    float a0 = b[c4], a1 = b[c4 + 1], a2 = b[c4 + 2], a3 = b[c4 + 3];
#pragma unroll
    for (int k = 0; k < 64; k++) {
        float a = nfs[rl * 64 + k];
        float4 w = *(const float4*)&Wt[k * 68 + c4];
        a0 = fmaf(a, w.x, a0);
        a1 = fmaf(a, w.y, a1);
        a2 = fmaf(a, w.z, a2);
        a3 = fmaf(a, w.w, a3);
    }
    int row = row0 + rl;
    if (row < n)
        x4[row * 16 + (c4 >> 2)] = make_float4(a0, a1, a2, a3);
}

// ---------------------------------------------------------------------------
// Kernel 2: edge aggregation.
// 16 threads per edge (one per 16B chunk). Gather x[src] (L2-resident,
// 256B coalesced per edge), scatter with red.global.add.v4.f32 (no return
// trip). Chunk 0 bumps the degree counter. Bounds-guarded.
// ---------------------------------------------------------------------------
__global__ __launch_bounds__(256) void edge_kernel(
    const void* __restrict__ ei_raw, const float4* __restrict__ x4,
    float4* __restrict__ agg4, float* __restrict__ deg, int E, int n)
{
    int tid = blockIdx.x * blockDim.x + threadIdx.x;
    int e = tid >> 4;
    if (e >= E) return;
    int c = tid & 15;

    int src, dst;
    if (g_is64) {
        const long long* ei = (const long long*)ei_raw;
        src = (int)ei[2 * (long long)e];
        dst = (int)ei[2 * (long long)e + 1];
    } else {
        int2 p = ((const int2*)ei_raw)[e];
        src = p.x;
        dst = p.y;
    }
    if ((unsigned)src >= (unsigned)n || (unsigned)dst >= (unsigned)n) return;

    float4 v = x4[src * 16 + c];
    float4* p = &agg4[dst * 16 + c];
    asm volatile("red.global.add.v4.f32 [%0], {%1, %2, %3, %4};"
                 :: "l"(p), "f"(v.x), "f"(v.y), "f"(v.z), "f"(v.w)
                 : "memory");
    if (c == 0)
        asm volatile("red.global.add.f32 [%0], %1;"
                     :: "l"(deg + dst), "f"(1.0f) : "memory");
}

// ---------------------------------------------------------------------------
// Kernel 3: out = relu(x + agg/max(deg,1) + bias)
// ---------------------------------------------------------------------------
__global__ __launch_bounds__(256) void final_kernel(
    const float4* __restrict__ x4, const float4* __restrict__ agg4,
    const float* __restrict__ deg, const float* __restrict__ bias,
    float4* __restrict__ out4, int n)
{
    int tid = blockIdx.x * blockDim.x + threadIdx.x;
    if (tid >= n * 16) return;
    int i = tid >> 4, c = tid & 15;

    float r = 1.0f / fmaxf(deg[i], 1.0f);
    float4 xv = x4[tid];
    float4 av = agg4[tid];
    float4 bv = *(const float4*)&bias[c * 4];
    float4 o;
    o.x = fmaxf(fmaf(av.x, r, xv.x) + bv.x, 0.f);
    o.y = fmaxf(fmaf(av.y, r, xv.y) + bv.y, 0.f);
    o.z = fmaxf(fmaf(av.z, r, xv.z) + bv.z, 0.f);
    o.w = fmaxf(fmaf(av.w, r, xv.w) + bv.w, 0.f);
    out4[tid] = o;
}

// ---------------------------------------------------------------------------
// Launch. Inputs (metadata order): node_features f32[N*64],
// edge_index [E*2] (int32 or int64 — detected), W f32[64*64],
// b_lin f32[64], bias f32[64]
// ---------------------------------------------------------------------------
extern "C" void kernel_launch(void* const* d_in, const int* in_sizes, int n_in,
                              void* d_out, int out_size)
{
    const float* nf   = (const float*)d_in[0];
    const void*  ei   = d_in[1];
    const float* W    = (const float*)d_in[2];
    const float* blin = (const float*)d_in[3];
    const float* bias = (const float*)d_in[4];
    float4*      out4 = (float4*)d_out;

    int n = in_sizes[0] / DDIM;       // 50000
    int E = in_sizes[1] / 2;          // 800000

    float4* x4;   cudaGetSymbolAddress((void**)&x4,   g_x4);
    float4* agg4; cudaGetSymbolAddress((void**)&agg4, g_agg4);
    float*  deg;  cudaGetSymbolAddress((void**)&deg,  g_deg);

    detect_kernel<<<1, 1>>>((const int*)ei, E);
    zero_kernel<<<592, 256>>>(agg4, deg, n);
    gemm_kernel<<<(n + 15) / 16, 256>>>(nf, W, blin, x4, n);
    {
        long long total = (long long)E * 16;
        int blocks = (int)((total + 255) / 256);
        edge_kernel<<<blocks, 256>>>(ei, x4, agg4, deg, E, n);
    }
    {
        int total = n * 16;
        final_kernel<<<(total + 255) / 256, 256>>>(x4, agg4, deg, bias, out4, n);
    }
}

// round 4
// speedup vs baseline: 1.1239x; 1.1239x over previous
#include <cuda_runtime.h>
#include <cuda_bf16.h>
#include <cstdint>

// Problem constants (fixed by the dataset)
#define NMAX 50048            // 50000 rounded up to 256
#define EMAX 800000
#define DDIM 64

// Scratch (no cudaMalloc allowed)
__device__ int    g_cnt[NMAX];        // in-degree histogram
__device__ int    g_start[NMAX];      // CSR start offsets
__device__ int    g_cursor[NMAX];     // scatter cursors
__device__ int    g_srcs[EMAX];       // src ids sorted by dst
__device__ float2 g_agg2[NMAX * 32];  // segment_sum of raw nf rows
__device__ int    g_part[256];        // scan partials
__device__ int    g_is64;             // edge_index dtype flag

// ---------------------------------------------------------------------------
// Detect edge_index dtype: for int64 data every odd int32 word is a zero
// high-word (indices < 50000); for int32 pairs they are random dst ids.
// ---------------------------------------------------------------------------
__global__ void detect_kernel(const int* __restrict__ ei32, int nE) {
    int all_zero = 1;
    int lim = (nE < 64) ? nE : 64;
    for (int i = 0; i < lim; i++)
        if (ei32[2 * i + 1] != 0) { all_zero = 0; break; }
    g_is64 = all_zero;
}

__global__ void zero_kernel(int* cnt, int n) {
    int i = blockIdx.x * blockDim.x + threadIdx.x;
    if (i < n) cnt[i] = 0;
}

__device__ __forceinline__ int2 load_edge(const void* ei_raw, int e) {
    if (g_is64) {
        const long long* ei = (const long long*)ei_raw;
        return make_int2((int)ei[2 * (long long)e], (int)ei[2 * (long long)e + 1]);
    }
    return ((const int2*)ei_raw)[e];
}

// ---------------------------------------------------------------------------
// Histogram of dst (in-degree)
// ---------------------------------------------------------------------------
__global__ __launch_bounds__(256) void hist_kernel(
    const void* __restrict__ ei_raw, int* __restrict__ cnt, int E, int n)
{
    int e = blockIdx.x * blockDim.x + threadIdx.x;
    if (e >= E) return;
    int2 p = load_edge(ei_raw, e);
    if ((unsigned)p.x >= (unsigned)n || (unsigned)p.y >= (unsigned)n) return;
    atomicAdd(&cnt[p.y], 1);
}

// ---------------------------------------------------------------------------
// Exclusive scan of cnt -> start (3 small kernels), n <= 256*256
// ---------------------------------------------------------------------------
__global__ __launch_bounds__(256) void scan_a(const int* cnt, int* part, int n) {
    __shared__ int s[256];
    int i = blockIdx.x * 256 + threadIdx.x;
    s[threadIdx.x] = (i < n) ? cnt[i] : 0;
    __syncthreads();
    for (int off = 128; off > 0; off >>= 1) {
        if (threadIdx.x < off) s[threadIdx.x] += s[threadIdx.x + off];
        __syncthreads();
    }
    if (threadIdx.x == 0) part[blockIdx.x] = s[0];
}

__global__ __launch_bounds__(256) void scan_b(int* part, int nb) {
    __shared__ int s[256];
    int t = threadIdx.x;
    int v = (t < nb) ? part[t] : 0;
    s[t] = v;
    __syncthreads();
    for (int off = 1; off < 256; off <<= 1) {
        int tmp = (t >= off) ? s[t - off] : 0;
        __syncthreads();
        s[t] += tmp;
        __syncthreads();
    }
    if (t < nb) part[t] = s[t] - v;   // exclusive
}

__global__ __launch_bounds__(256) void scan_c(
    const int* cnt, const int* part, int* start, int* cursor, int n)
{
    __shared__ int s[256];
    int t = threadIdx.x;
    int i = blockIdx.x * 256 + t;
    int v = (i < n) ? cnt[i] : 0;
    s[t] = v;
    __syncthreads();
    for (int off = 1; off < 256; off <<= 1) {
        int tmp = (t >= off) ? s[t - off] : 0;
        __syncthreads();
        s[t] += tmp;
        __syncthreads();
    }
    if (i < n) {
        int st = part[blockIdx.x] + s[t] - v;  // exclusive
        start[i]  = st;
        cursor[i] = st;
    }
}

// ---------------------------------------------------------------------------
// Scatter src ids into CSR order (counting sort by dst)
// ---------------------------------------------------------------------------
__global__ __launch_bounds__(256) void scatter_kernel(
    const void* __restrict__ ei_raw, int* __restrict__ cursor,
    int* __restrict__ srcs, int E, int n)
{
    int e = blockIdx.x * blockDim.x + threadIdx.x;
    if (e >= E) return;
    int2 p = load_edge(ei_raw, e);
    if ((unsigned)p.x >= (unsigned)n || (unsigned)p.y >= (unsigned)n) return;
    int slot = atomicAdd(&cursor[p.y], 1);
    srcs[slot] = p.x;
}

// ---------------------------------------------------------------------------
// Gather: warp per node, lane c owns float2 chunk c of the 64-dim row.
// agg_nf[i] = sum over in-edges of nf[src]. Pure loads, no float atomics.
// ---------------------------------------------------------------------------
__global__ __launch_bounds__(256) void gather_kernel(
    const int* __restrict__ srcs, const int* __restrict__ start,
    const int* __restrict__ cnt, const float2* __restrict__ nf2,
    float2* __restrict__ agg2, int n)
{
    int node = blockIdx.x * 8 + (threadIdx.x >> 5);
    if (node >= n) return;
    int lane = threadIdx.x & 31;
    int s = start[node];
    int d = cnt[node];
    float2 acc = make_float2(0.f, 0.f);
    for (int j = 0; j < d; j++) {
        int src = srcs[s + j];            // broadcast (same addr all lanes)
        float2 v = nf2[src * 32 + lane];  // coalesced 256B per edge
        acc.x += v.x;
        acc.y += v.y;
    }
    agg2[node * 32 + lane] = acc;
}

// ---------------------------------------------------------------------------
// Fused GEMM + epilogue:
// out = relu( (nf + agg_nf/degmax) @ W^T + (1 + deg/degmax)*b_lin + bias )
// (by linearity: segment_sum(x[src]) = W @ segment_sum(nf[src]) + deg*b_lin)
// Block: 256 threads = 16 rows x 16 col-quads.
// ---------------------------------------------------------------------------
__global__ __launch_bounds__(256) void gemm_fused_kernel(
    const float* __restrict__ nf, const float* __restrict__ agg,
    const int* __restrict__ cnt, const float* __restrict__ W,
    const float* __restrict__ blin, const float* __restrict__ bias,
    float4* __restrict__ out4, int n)
{
    __shared__ float Wt[64 * 68];   // Wt[k*68 + c] = W[c*64 + k]
    __shared__ float ys[16 * 64];   // fused input rows
    __shared__ float invs[16];      // 1/max(deg,1)
    __shared__ float bco[16];       // 1 + deg/degmax  (2 if deg>0 else 1)

    int t = threadIdx.x;
    int row0 = blockIdx.x * 16;

    if (t < 16) {
        int r = row0 + t;
        int d = (r < n) ? cnt[r] : 0;
        invs[t] = 1.0f / fmaxf((float)d, 1.0f);
        bco[t]  = (d > 0) ? 2.0f : 1.0f;
    }
    for (int i = t; i < 64 * 64; i += 256) {
        int col = i >> 6, k = i & 63;
        Wt[k * 68 + col] = W[i];
    }
    __syncthreads();   // invs ready

    for (int i = t; i < 16 * 64; i += 256) {
        int rl = i >> 6;
        int r = row0 + rl;
        int k = i & 63;
        ys[i] = (r < n) ? fmaf(agg[r * 64 + k], invs[rl], nf[r * 64 + k]) : 0.f;
    }
    __syncthreads();

    int rl = t >> 4;
    int c4 = (t & 15) * 4;
    float a0 = 0.f, a1 = 0.f, a2 = 0.f, a3 = 0.f;
#pragma unroll
    for (int k = 0; k < 64; k++) {
        float a = ys[rl * 64 + k];
        float4 w = *(const float4*)&Wt[k * 68 + c4];
        a0 = fmaf(a, w.x, a0);
        a1 = fmaf(a, w.y, a1);
        a2 = fmaf(a, w.z, a2);
        a3 = fmaf(a, w.w, a3);
    }
    int row = row0 + rl;
    if (row < n) {
        float bc = bco[rl];
        float4 o;
        o.x = fmaxf(fmaf(bc, blin[c4 + 0], a0) + bias[c4 + 0], 0.f);
        o.y = fmaxf(fmaf(bc, blin[c4 + 1], a1) + bias[c4 + 1], 0.f);
        o.z = fmaxf(fmaf(bc, blin[c4 + 2], a2) + bias[c4 + 2], 0.f);
        o.w = fmaxf(fmaf(bc, blin[c4 + 3], a3) + bias[c4 + 3], 0.f);
        out4[row * 16 + (c4 >> 2)] = o;
    }
}

// ---------------------------------------------------------------------------
// Launch
// ---------------------------------------------------------------------------
extern "C" void kernel_launch(void* const* d_in, const int* in_sizes, int n_in,
                              void* d_out, int out_size)
{
    const float* nf   = (const float*)d_in[0];
    const void*  ei   = d_in[1];
    const float* W    = (const float*)d_in[2];
    const float* blin = (const float*)d_in[3];
    const float* bias = (const float*)d_in[4];
    float4*      out4 = (float4*)d_out;

    int n = in_sizes[0] / DDIM;       // 50000
    int E = in_sizes[1] / 2;          // 800000

    int*    cnt;    cudaGetSymbolAddress((void**)&cnt,    g_cnt);
    int*    start;  cudaGetSymbolAddress((void**)&start,  g_start);
    int*    cursor; cudaGetSymbolAddress((void**)&cursor, g_cursor);
    int*    srcs;   cudaGetSymbolAddress((void**)&srcs,   g_srcs);
    float2* agg2;   cudaGetSymbolAddress((void**)&agg2,   g_agg2);
    int*    part;   cudaGetSymbolAddress((void**)&part,   g_part);

    int nb = (n + 255) / 256;         // 196 scan blocks (<= 256)
    int eb = (E + 255) / 256;         // 3125 edge blocks

    detect_kernel<<<1, 1>>>((const int*)ei, E);
    zero_kernel<<<nb, 256>>>(cnt, n);
    hist_kernel<<<eb, 256>>>(ei, cnt, E, n);
    scan_a<<<nb, 256>>>(cnt, part, n);
    scan_b<<<1, 256>>>(part, nb);
    scan_c<<<nb, 256>>>(cnt, part, start, cursor, n);
    scatter_kernel<<<eb, 256>>>(ei, cursor, srcs, E, n);
    gather_kernel<<<(n + 7) / 8, 256>>>(srcs, start, cnt, (const float2*)nf, agg2, n);
    gemm_fused_kernel<<<(n + 15) / 16, 256>>>(
        nf, (const float*)agg2, cnt, W, blin, bias, out4, n);
}